// round 5
// baseline (speedup 1.0000x reference)
#include <cuda_runtime.h>
#include <math.h>

#define VOCAB 50000
#define E 128
#define H 128
#define B 256
#define T 2048

typedef unsigned long long ull;

// Packed f32x2 FMA (Blackwell): d.lo=a.lo*b.lo+c.lo, d.hi=a.hi*b.hi+c.hi
#define FMA2(d, a, b, c) \
    asm("fma.rn.f32x2 %0, %1, %2, %3;" : "=l"(d) : "l"(a), "l"(b), "l"(c))
#define PACK2(d, lo, hi) \
    asm("mov.b64 %0, {%1, %2};" : "=l"(d) : "f"(lo), "f"(hi))
#define UNPACK2(lo, hi, v) \
    asm("mov.b64 {%0, %1}, %2;" : "=f"(lo), "=f"(hi) : "l"(v))

// Branchless fast tanh: tanh(x) = 1 - 2/(1 + e^{2x}), via MUFU ex2/rcp.
// ex2.approx/rcp.approx rel err ~2^-22 -> total ~1e-6, safe vs 1e-3 gate.
__device__ __forceinline__ float fast_tanh(float x) {
    float e, r;
    // e = 2^(x * 2*log2(e))
    asm("ex2.approx.f32 %0, %1;" : "=f"(e) : "f"(x * 2.8853900817779268f));
    asm("rcp.approx.f32 %0, %1;" : "=f"(r) : "f"(e + 1.0f));
    return 1.0f - 2.0f * r;   // correct limits: x->-inf => -1, x->+inf => +1
}

__device__ __forceinline__ float fast_sigmoid(float x) {
    float e, r;
    asm("ex2.approx.f32 %0, %1;" : "=f"(e) : "f"(-x * 1.4426950408889634f));
    asm("rcp.approx.f32 %0, %1;" : "=f"(r) : "f"(e + 1.0f));
    return r;
}

// Device scratch (sanctioned: __device__ globals, no allocation)
__device__ float g_X0[VOCAB * H];   // emb @ W_ih[0] + b0, per vocab id
__device__ int   g_order[B];        // batch rows sorted by length, descending

// ---------------------------------------------------------------------------
// Kernel B: block 0 first rank-sorts rows by length (descending, stable),
// then all blocks compute X0[v][j] = b0[j] + sum_k emb[v][k]*W_ih0[k][j].
// 256 threads = (k-half, column j); weight k-pairs packed in 32 ull regs.
// (sort merged here so the launch sequence is x0,rnn,x0,rnn,... and ncu -s 5
//  lands on rnn_kernel.)
// ---------------------------------------------------------------------------
__global__ void __launch_bounds__(256)
x0_kernel(const float* __restrict__ emb,
          const float* __restrict__ W_ih,
          const float* __restrict__ b,
          const int* __restrict__ lengths) {
    __shared__ __align__(16) float embs[H];
    __shared__ float part[2 * H];
    __shared__ int s_len[B];

    int tid   = threadIdx.x;
    int half  = tid >> 7;
    int j     = tid & 127;
    int kbase = half * 64;

    if (blockIdx.x == 0) {
        // rank sort (256 threads, one element each)
        s_len[tid] = lengths[tid];
        __syncthreads();
        int li = s_len[tid];
        int rank = 0;
        for (int jj = 0; jj < B; jj++) {
            int lj = s_len[jj];
            rank += (lj > li) || (lj == li && jj < tid);
        }
        g_order[rank] = tid;
        __syncthreads();
    }

    ull w[32];
    #pragma unroll
    for (int kk = 0; kk < 32; kk++) {
        int k = kbase + 2 * kk;
        PACK2(w[kk], W_ih[k * H + j], W_ih[(k + 1) * H + j]);
    }
    float b0 = b[j];

    for (int r = blockIdx.x; r < VOCAB; r += gridDim.x) {
        if (tid < H) embs[tid] = emb[r * E + tid];
        __syncthreads();
        ull acc = 0;
        #pragma unroll
        for (int i = 0; i < 16; i++) {
            ulonglong2 ev = *(const ulonglong2*)&embs[kbase + 4 * i];
            FMA2(acc, ev.x, w[2 * i], acc);
            FMA2(acc, ev.y, w[2 * i + 1], acc);
        }
        float lo, hi;
        UNPACK2(lo, hi, acc);
        part[tid] = lo + hi;
        __syncthreads();
        if (tid < H) g_X0[r * H + j] = b0 + part[j] + part[H + j];
        __syncthreads();
    }
}

// ---------------------------------------------------------------------------
// Kernel C: persistent per-row RNN, cross-layer pipelined.
// 256 CTAs (one row each, longest first), 256 threads = 8 warps.
// Lane layout: warp w, lane l -> column j = 16*w + (l&15), k-half = l>>4.
// Superstep t computes BOTH h1(t) and h0(t+1) from {h0(t), h1(t-1)}:
//   h1(t)   = tanh(b1 + W_ih1 h0(t) + W_hh1 h1(t-1))
//   h0(t+1) = tanh(X0[tok[t+1]] + W_hh0 h0(t))
// Cross-half reduce via shfl.bfly(16); h double-buffered -> 1 barrier/step.
// ---------------------------------------------------------------------------
__global__ void __launch_bounds__(256, 1)
rnn_kernel(const int* __restrict__ x, const int* __restrict__ lengths,
           const float* __restrict__ W_ih, const float* __restrict__ W_hh,
           const float* __restrict__ b, const float* __restrict__ cls_w,
           const float* __restrict__ cls_b, float* __restrict__ out) {
    __shared__ int xrow[T];
    __shared__ __align__(16) float h0s[2][H];
    __shared__ __align__(16) float h1s[2][H];

    int tid   = threadIdx.x;
    int warp  = tid >> 5;
    int lane  = tid & 31;
    int j     = warp * 16 + (lane & 15);
    int half  = lane >> 4;
    int kbase = half * 64;

    int row = g_order[blockIdx.x];
    int len = lengths[row];

    // Pre-packed weight k-pair columns in registers: 3 x 32 ull.
    ull w0p[32], w1p[32], w2p[32];
    #pragma unroll
    for (int kk = 0; kk < 32; kk++) {
        int k = kbase + 2 * kk;
        PACK2(w0p[kk], W_hh[k * H + j],           W_hh[(k + 1) * H + j]);           // W_hh0
        PACK2(w1p[kk], W_ih[H * H + k * H + j],   W_ih[H * H + (k + 1) * H + j]);   // W_ih1
        PACK2(w2p[kk], W_hh[H * H + k * H + j],   W_hh[H * H + (k + 1) * H + j]);   // W_hh1
    }
    float b1v = b[H + j];

    // Stage token ids for this row into smem (8 KB).
    for (int i = tid; i < T; i += 256) xrow[i] = x[row * T + i];
    __syncthreads();

    // Prologue: h0(0) = tanh(X0[tok0]) (b0 folded into X0, h_init = 0); h1(-1)=0.
    if (half == 0) h0s[0][j] = fast_tanh(g_X0[xrow[0] * H + j]);
    else           h1s[0][j] = 0.f;
    float x0cur = 0.f, x0nxt = 0.f;
    if (half == 0) x0cur = g_X0[xrow[(len > 1) ? 1 : 0] * H + j];
    __syncthreads();

    for (int t = 0; t < len; t++) {
        int p = t & 1;
        const float* hr0 = &h0s[p][kbase];
        const float* hr1 = &h1s[p][kbase];

        // Prefetch X0 for superstep t+1 (needs tok[t+2]).
        if (half == 0) {
            int tn = t + 2;
            if (tn > len - 1) tn = len - 1;
            x0nxt = g_X0[xrow[tn] * H + j];
        }

        // Three matmul partials over this thread's k-half (FFMA2-packed).
        // acc0 split in two chains to shorten the dependency chain.
        ull acc0a = 0, acc0b = 0, acc1 = 0, acc2 = 0;
        #pragma unroll
        for (int i = 0; i < 16; i++) {
            ulonglong2 hp = *(const ulonglong2*)(hr0 + 4 * i);
            FMA2(acc0a, hp.x, w0p[2 * i],     acc0a);
            FMA2(acc1,  hp.x, w1p[2 * i],     acc1);
            FMA2(acc0b, hp.y, w0p[2 * i + 1], acc0b);
            FMA2(acc1,  hp.y, w1p[2 * i + 1], acc1);
            ulonglong2 gp = *(const ulonglong2*)(hr1 + 4 * i);
            FMA2(acc2,  gp.x, w2p[2 * i],     acc2);
            FMA2(acc2,  gp.y, w2p[2 * i + 1], acc2);
        }

        // Reduce: packed lanes, then across k-halves (bfly 16).
        float lo, hi, s0, s1, s2;
        UNPACK2(lo, hi, acc0a); s0 = lo + hi;
        UNPACK2(lo, hi, acc0b); s0 += lo + hi;
        UNPACK2(lo, hi, acc1);  s1 = lo + hi;
        UNPACK2(lo, hi, acc2);  s2 = lo + hi;
        s0 += __shfl_xor_sync(0xffffffffu, s0, 16);
        s1 += __shfl_xor_sync(0xffffffffu, s1, 16);
        s2 += __shfl_xor_sync(0xffffffffu, s2, 16);

        // half 0 produces h0(t+1); half 1 produces h1(t).
        float argv = half ? (b1v + s1 + s2) : (x0cur + s0);
        float hv = fast_tanh(argv);

        // Double-buffered write: no WAR hazard, single barrier per step.
        float* dst = half ? &h1s[p ^ 1][0] : &h0s[p ^ 1][0];
        dst[j] = hv;
        __syncthreads();

        x0cur = x0nxt;
    }

    // ---- classifier: sigmoid(h1_final . cls_w + cls_b) ----
    const float* h1f = h1s[len & 1];
    if (tid < 32) {
        float v = 0.f;
        #pragma unroll
        for (int m = 0; m < 4; m++) {
            int jj = tid + 32 * m;
            v += h1f[jj] * cls_w[jj];
        }
        #pragma unroll
        for (int off = 16; off; off >>= 1)
            v += __shfl_xor_sync(0xffffffffu, v, off);
        if (tid == 0) out[row] = fast_sigmoid(v + cls_b[0]);
    }
}

// ---------------------------------------------------------------------------
extern "C" void kernel_launch(void* const* d_in, const int* in_sizes, int n_in,
                              void* d_out, int out_size) {
    const int*   x       = (const int*)d_in[0];
    const int*   lengths = (const int*)d_in[1];
    const float* emb     = (const float*)d_in[2];
    const float* W_ih    = (const float*)d_in[3];
    const float* W_hh    = (const float*)d_in[4];
    const float* b       = (const float*)d_in[5];
    const float* cls_w   = (const float*)d_in[6];
    const float* cls_b   = (const float*)d_in[7];
    float*       out     = (float*)d_out;

    x0_kernel<<<1024, 256>>>(emb, W_ih, b, lengths);
    rnn_kernel<<<B, 256>>>(x, lengths, W_ih, W_hh, b, cls_w, cls_b, out);
}

// round 6
// speedup vs baseline: 1.1876x; 1.1876x over previous
#include <cuda_runtime.h>
#include <math.h>

#define VOCAB 50000
#define E 128
#define H 128
#define B 256
#define T 2048

#define GRID_C 148            // one CTA per SM; CTAs 40..147 process 2 rows
#define NSINGLE (2 * GRID_C - B)   // = 40 longest rows run alone

typedef unsigned long long ull;

// Packed f32x2 FMA (Blackwell): d.lo=a.lo*b.lo+c.lo, d.hi=a.hi*b.hi+c.hi
#define FMA2(d, a, b, c) \
    asm("fma.rn.f32x2 %0, %1, %2, %3;" : "=l"(d) : "l"(a), "l"(b), "l"(c))
#define PACK2(d, lo, hi) \
    asm("mov.b64 %0, {%1, %2};" : "=l"(d) : "f"(lo), "f"(hi))
#define UNPACK2(lo, hi, v) \
    asm("mov.b64 {%0, %1}, %2;" : "=f"(lo), "=f"(hi) : "l"(v))

// Branchless fast tanh: tanh(x) = 1 - 2/(1 + e^{2x}) via MUFU ex2/rcp.
// rel err ~1e-6, safe vs the 1e-3 gate.
__device__ __forceinline__ float fast_tanh(float x) {
    float e, r;
    asm("ex2.approx.f32 %0, %1;" : "=f"(e) : "f"(x * 2.8853900817779268f));
    asm("rcp.approx.f32 %0, %1;" : "=f"(r) : "f"(e + 1.0f));
    return 1.0f - 2.0f * r;
}

__device__ __forceinline__ float fast_sigmoid(float x) {
    float e, r;
    asm("ex2.approx.f32 %0, %1;" : "=f"(e) : "f"(-x * 1.4426950408889634f));
    asm("rcp.approx.f32 %0, %1;" : "=f"(r) : "f"(e + 1.0f));
    return r;
}

// Device scratch (sanctioned: __device__ globals, no allocation)
__device__ float g_X0[VOCAB * H];   // emb @ W_ih[0] + b0, per vocab id
__device__ int   g_order[B];        // batch rows sorted by length, descending

// ---------------------------------------------------------------------------
// Kernel B: block 0 rank-sorts rows by length (desc, stable), then all blocks
// compute X0[v][j] = b0[j] + sum_k emb[v][k]*W_ih0[k][j]. 256 thr = (k-half, j).
// ---------------------------------------------------------------------------
__global__ void __launch_bounds__(256)
x0_kernel(const float* __restrict__ emb,
          const float* __restrict__ W_ih,
          const float* __restrict__ b,
          const int* __restrict__ lengths) {
    __shared__ __align__(16) float embs[H];
    __shared__ float part[2 * H];
    __shared__ int s_len[B];

    int tid   = threadIdx.x;
    int half  = tid >> 7;
    int j     = tid & 127;
    int kbase = half * 64;

    if (blockIdx.x == 0) {
        s_len[tid] = lengths[tid];
        __syncthreads();
        int li = s_len[tid];
        int rank = 0;
        for (int jj = 0; jj < B; jj++) {
            int lj = s_len[jj];
            rank += (lj > li) || (lj == li && jj < tid);
        }
        g_order[rank] = tid;
        __syncthreads();
    }

    ull w[32];
    #pragma unroll
    for (int kk = 0; kk < 32; kk++) {
        int k = kbase + 2 * kk;
        PACK2(w[kk], W_ih[k * H + j], W_ih[(k + 1) * H + j]);
    }
    float b0 = b[j];

    for (int r = blockIdx.x; r < VOCAB; r += gridDim.x) {
        if (tid < H) embs[tid] = emb[r * E + tid];
        __syncthreads();
        ull acc = 0;
        #pragma unroll
        for (int i = 0; i < 16; i++) {
            ulonglong2 ev = *(const ulonglong2*)&embs[kbase + 4 * i];
            FMA2(acc, ev.x, w[2 * i], acc);
            FMA2(acc, ev.y, w[2 * i + 1], acc);
        }
        float lo, hi;
        UNPACK2(lo, hi, acc);
        part[tid] = lo + hi;
        __syncthreads();
        if (tid < H) g_X0[r * H + j] = b0 + part[j] + part[H + j];
        __syncthreads();
    }
}

// ---------------------------------------------------------------------------
// Kernel C: persistent RNN, 148 CTAs (1/SM). CTA c runs sorted rank c, and
// (if c >= NSINGLE) also rank 295-c: explicit longest+shortest pairing keeps
// the chip critical path at the single longest row (~2048 steps).
// 256 threads = 8 warps; warp w, lane l -> column j = 16*w + (l&15),
// k-half = l>>4. Superstep t computes h1(t) and h0(t+1) from {h0(t), h1(t-1)}.
// Cross-half reduce via shfl.bfly(16); h double-buffered -> 1 barrier/step.
// ---------------------------------------------------------------------------
__global__ void __launch_bounds__(256, 1)
rnn_kernel(const int* __restrict__ x, const int* __restrict__ lengths,
           const float* __restrict__ W_ih, const float* __restrict__ W_hh,
           const float* __restrict__ b, const float* __restrict__ cls_w,
           const float* __restrict__ cls_b, float* __restrict__ out) {
    __shared__ int xrow[T];
    __shared__ __align__(16) float h0s[2][H];
    __shared__ __align__(16) float h1s[2][H];

    int tid   = threadIdx.x;
    int warp  = tid >> 5;
    int lane  = tid & 31;
    int j     = warp * 16 + (lane & 15);
    int half  = lane >> 4;
    int kbase = half * 64;

    int c = blockIdx.x;

    // Row-independent weights: pre-packed k-pair columns, 3 x 32 ull regs.
    ull w0p[32], w1p[32], w2p[32];
    #pragma unroll
    for (int kk = 0; kk < 32; kk++) {
        int k = kbase + 2 * kk;
        PACK2(w0p[kk], W_hh[k * H + j],           W_hh[(k + 1) * H + j]);           // W_hh0
        PACK2(w1p[kk], W_ih[H * H + k * H + j],   W_ih[H * H + (k + 1) * H + j]);   // W_ih1
        PACK2(w2p[kk], W_hh[H * H + k * H + j],   W_hh[H * H + (k + 1) * H + j]);   // W_hh1
    }
    float b1v = b[H + j];

    int nrows = (c >= NSINGLE) ? 2 : 1;
    for (int ri = 0; ri < nrows; ri++) {
        int rank = (ri == 0) ? c : (2 * GRID_C - 1 - c + NSINGLE - NSINGLE); // 295 - c
        if (ri == 1) rank = (2 * GRID_C - 1) - c + (B - 2 * (GRID_C - NSINGLE)); // keep simple below
        rank = (ri == 0) ? c : (B - 1) - (c - NSINGLE);   // c=40 -> 255, c=147 -> 148
        int row = g_order[rank];
        int len = lengths[row];

        __syncthreads();   // prior row's classifier read done before restaging
        for (int i = tid; i < T; i += 256) xrow[i] = x[row * T + i];
        __syncthreads();

        // Prologue: h0(0)=tanh(X0[tok0]) (b0 in X0, h_init=0); h1(-1)=0.
        if (half == 0) h0s[0][j] = fast_tanh(g_X0[xrow[0] * H + j]);
        else           h1s[0][j] = 0.f;
        float x0cur = 0.f, x0nxt = 0.f;
        if (half == 0) x0cur = g_X0[xrow[(len > 1) ? 1 : 0] * H + j];
        __syncthreads();

        for (int t = 0; t < len; t++) {
            int p = t & 1;
            const float* hr0 = &h0s[p][kbase];
            const float* hr1 = &h1s[p][kbase];

            // Prefetch X0 for superstep t+1 (needs tok[t+2]).
            if (half == 0) {
                int tn = t + 2;
                if (tn > len - 1) tn = len - 1;
                x0nxt = g_X0[xrow[tn] * H + j];
            }

            // Three matmul partials over this k-half (FFMA2-packed).
            ull acc0 = 0, acc1 = 0, acc2 = 0;
            #pragma unroll
            for (int i = 0; i < 16; i++) {
                ulonglong2 hp = *(const ulonglong2*)(hr0 + 4 * i);
                FMA2(acc0, hp.x, w0p[2 * i],     acc0);
                FMA2(acc0, hp.y, w0p[2 * i + 1], acc0);
                FMA2(acc1, hp.x, w1p[2 * i],     acc1);
                FMA2(acc1, hp.y, w1p[2 * i + 1], acc1);
                ulonglong2 gp = *(const ulonglong2*)(hr1 + 4 * i);
                FMA2(acc2, gp.x, w2p[2 * i],     acc2);
                FMA2(acc2, gp.y, w2p[2 * i + 1], acc2);
            }

            // Reduce: packed lanes, then across k-halves (bfly 16).
            float lo, hi, s0, s1, s2;
            UNPACK2(lo, hi, acc0); s0 = lo + hi;
            UNPACK2(lo, hi, acc1); s1 = lo + hi;
            UNPACK2(lo, hi, acc2); s2 = lo + hi;
            s0 += __shfl_xor_sync(0xffffffffu, s0, 16);
            s1 += __shfl_xor_sync(0xffffffffu, s1, 16);
            s2 += __shfl_xor_sync(0xffffffffu, s2, 16);

            // half 0 produces h0(t+1); half 1 produces h1(t).
            float argv = half ? (b1v + s1 + s2) : (x0cur + s0);
            float hv = fast_tanh(argv);

            float* dst = half ? &h1s[p ^ 1][0] : &h0s[p ^ 1][0];
            dst[j] = hv;
            __syncthreads();

            x0cur = x0nxt;
        }

        // ---- classifier: sigmoid(h1_final . cls_w + cls_b) ----
        const float* h1f = h1s[len & 1];
        if (tid < 32) {
            float v = 0.f;
            #pragma unroll
            for (int m = 0; m < 4; m++) {
                int jj = tid + 32 * m;
                v += h1f[jj] * cls_w[jj];
            }
            #pragma unroll
            for (int off = 16; off; off >>= 1)
                v += __shfl_xor_sync(0xffffffffu, v, off);
            if (tid == 0) out[row] = fast_sigmoid(v + cls_b[0]);
        }
    }
}

// ---------------------------------------------------------------------------
extern "C" void kernel_launch(void* const* d_in, const int* in_sizes, int n_in,
                              void* d_out, int out_size) {
    const int*   x       = (const int*)d_in[0];
    const int*   lengths = (const int*)d_in[1];
    const float* emb     = (const float*)d_in[2];
    const float* W_ih    = (const float*)d_in[3];
    const float* W_hh    = (const float*)d_in[4];
    const float* b       = (const float*)d_in[5];
    const float* cls_w   = (const float*)d_in[6];
    const float* cls_b   = (const float*)d_in[7];
    float*       out     = (float*)d_out;

    x0_kernel<<<1024, 256>>>(emb, W_ih, b, lengths);
    rnn_kernel<<<GRID_C, 256>>>(x, lengths, W_ih, W_hh, b, cls_w, cls_b, out);
}